// round 9
// baseline (speedup 1.0000x reference)
#include <cuda_runtime.h>
#include <cuda_bf16.h>
#include <math.h>
#include <stdint.h>

// ---------------- problem constants ----------------
#define NB    2048
#define NPIX1 256
#define C1    128
#define SPIX  64
#define NROWS (NB*SPIX)
#define DDIM  256
#define KMAX  1024
#define CH    16384
#define HID   512
#define K2    2048

// ---------------- scratch ----------------
__device__ float         g_relu1[(size_t)NB * C1 * NPIX1];
__device__ float         g_xcol [(size_t)NB * K2 * 64];      // [n][k'][64 spix]
__device__ float         g_w2p  [K2 * 256];                  // [k'][oc]
__device__ float         g_feaT [(size_t)NROWS * DDIM];      // [row][oc] fp32
__device__ __nv_bfloat16 g_feah[(size_t)NROWS * DDIM], g_feal[(size_t)NROWS * DDIM];
__device__ __nv_bfloat16 g_cbh[KMAX * DDIM], g_cbl[KMAX * DDIM];
__device__ float         g_cbF[KMAX * DDIM];
__device__ float         g_cn2[KMAX];
__device__ float         g_scores[(size_t)NROWS * KMAX];
__device__ int           g_bi[NROWS];
__device__ __nv_bfloat16 g_qh[(size_t)NB * CH], g_ql[(size_t)NB * CH];
__device__ __nv_bfloat16 g_f1wh[(size_t)HID * CH], g_f1wl[(size_t)HID * CH];
__device__ float         g_h1[(size_t)NB * HID];
__device__ int           g_counts[KMAX];
__device__ float         g_lossSum;
__device__ int           g_Kc;

// ---------------- helpers ----------------
__device__ __forceinline__ uint32_t s2u(const void* p) {
    return (uint32_t)__cvta_generic_to_shared(p);
}
__device__ __forceinline__ void cpasync16(uint32_t s, const void* g) {
    asm volatile("cp.async.cg.shared.global [%0], [%1], 16;" :: "r"(s), "l"(g));
}
__device__ __forceinline__ void ldsm4(uint32_t* r, uint32_t s) {
    asm volatile("ldmatrix.sync.aligned.m8n8.x4.shared.b16 {%0,%1,%2,%3}, [%4];"
                 : "=r"(r[0]), "=r"(r[1]), "=r"(r[2]), "=r"(r[3]) : "r"(s));
}
__device__ __forceinline__ void mma16816(float* c, const uint32_t* a, const uint32_t* b) {
    asm volatile("mma.sync.aligned.m16n8k16.row.col.f32.bf16.bf16.f32 "
                 "{%0,%1,%2,%3}, {%4,%5,%6,%7}, {%8,%9}, {%0,%1,%2,%3};"
                 : "+f"(c[0]), "+f"(c[1]), "+f"(c[2]), "+f"(c[3])
                 : "r"(a[0]), "r"(a[1]), "r"(a[2]), "r"(a[3]), "r"(b[0]), "r"(b[1]));
}
__device__ __forceinline__ void split2(float v, __nv_bfloat16& h, __nv_bfloat16& l) {
    h = __float2bfloat16(v);
    l = __float2bfloat16(v - __bfloat162float(h));
}
__device__ __forceinline__ unsigned long long pk2(float x, float y) {
    unsigned long long r;
    asm("mov.b64 %0, {%1, %2};" : "=l"(r) : "f"(x), "f"(y));
    return r;
}
__device__ __forceinline__ float2 upk2(unsigned long long v) {
    float2 f;
    asm("mov.b64 {%0, %1}, %2;" : "=f"(f.x), "=f"(f.y) : "l"(v));
    return f;
}
#define FMA2(d, a, b) asm("fma.rn.f32x2 %0, %1, %2, %0;" : "+l"(d) : "l"(a), "l"(b))

// ---------------- zero stats ----------------
__global__ void zero_stats_kernel() {
    int t = threadIdx.x;
    if (t < KMAX) g_counts[t] = 0;
    if (t == 0)   g_lossSum = 0.f;
}

// ---------------- conv1: FFMA2, 2 pixels/thread; per-(pixel,oc) chain == R1 ----
__global__ void __launch_bounds__(128) conv1_kernel(const float* __restrict__ x,
                                                    const float* __restrict__ w1,
                                                    const float* __restrict__ b1) {
    extern __shared__ float s1[];
    float* sIn = s1;                                                    // 3072 f
    unsigned long long* sW2 = (unsigned long long*)(s1 + 3072);         // 6144 u64 (w dup)
    float* sB = (float*)(sW2 + 6144);                                   // 128 f
    int n = blockIdx.x, tid = threadIdx.x;
    for (int i = tid; i < 3072; i += 128) sIn[i] = x[(size_t)n * 3072 + i];
    for (int i = tid; i < 6144; i += 128) { float w = w1[i]; sW2[i] = pk2(w, w); }
    if (tid < 128) sB[tid] = b1[tid];
    __syncthreads();

    int p0 = tid * 2;                      // even -> p0,p1 share oh
    int oh = p0 >> 4, ow0 = p0 & 15, ow1 = ow0 + 1;
    unsigned long long a2[48];
#pragma unroll
    for (int ci = 0; ci < 3; ci++)
#pragma unroll
        for (int kh = 0; kh < 4; kh++)
#pragma unroll
            for (int kw = 0; kw < 4; kw++) {
                int ih = 2 * oh - 1 + kh;
                int iw0 = 2 * ow0 - 1 + kw, iw1 = 2 * ow1 - 1 + kw;
                bool rv = (ih >= 0 && ih < 32);
                float v0 = (rv && iw0 >= 0 && iw0 < 32) ? sIn[ci * 1024 + ih * 32 + iw0] : 0.f;
                float v1 = (rv && iw1 < 32) ? sIn[ci * 1024 + ih * 32 + iw1] : 0.f;
                a2[ci * 16 + kh * 4 + kw] = pk2(v0, v1);
            }

    float* outp = g_relu1 + (size_t)n * (C1 * NPIX1);
    for (int ch = 0; ch < 4; ch++) {
        unsigned long long acc2[32];
#pragma unroll
        for (int o = 0; o < 32; o++) { float b = sB[ch * 32 + o]; acc2[o] = pk2(b, b); }
#pragma unroll
        for (int t = 0; t < 48; t++)
#pragma unroll
            for (int o = 0; o < 32; o++)
                FMA2(acc2[o], a2[t], sW2[(ch * 32 + o) * 48 + t]);
#pragma unroll
        for (int o = 0; o < 32; o++) {
            float2 v = upk2(acc2[o]);
            float2 st = {fmaxf(v.x, 0.f), fmaxf(v.y, 0.f)};
            *(float2*)&outp[(size_t)(ch * 32 + o) * 256 + p0] = st;
        }
    }
}

// ---------------- im2col fp32 (R8 verbatim): k' = kcblk*128+tap*8+ciL ---------
__global__ void im2col_kernel() {
    int kcblk = blockIdx.x;
    int n     = blockIdx.y;
    int tid = threadIdx.x;
    for (int t = tid; t < 8192; t += 256) {
        int kl = t >> 6, s = t & 63;
        int tap = kl >> 3, ciL = kl & 7;
        int ci = kcblk * 8 + ciL;
        int kh = tap >> 2, kw = tap & 3;
        int oh = s >> 3, ow = s & 7;
        int ih = 2 * oh - 1 + kh, iw = 2 * ow - 1 + kw;
        float v = 0.f;
        if (ih >= 0 && ih < 16 && iw >= 0 && iw < 16)
            v = g_relu1[((size_t)n * 128 + ci) * 256 + ih * 16 + iw];
        g_xcol[(((size_t)n * 16 + kcblk) * 128 + kl) * 64 + s] = v;
    }
}

// ---------------- prep: permuted w2p[k'][oc] (R8 verbatim) ----------------
__global__ void prep_w2p_kernel(const float* __restrict__ w2) {
    int gid = blockIdx.x * 256 + threadIdx.x;
    int oc = gid & 255, kp = gid >> 8;
    int kcblk = kp >> 7, r = kp & 127;
    int tap = r >> 3, ciL = r & 7;
    int gk = (kcblk * 8 + ciL) * 16 + tap;
    g_w2p[gid] = w2[(size_t)oc * 2048 + gk];
}

// ---------------- conv2 GEMM: 128 thr, 8 spix x 16 oc; fused feaT/feah/feal ---
// per-(s,oc) chain sequential in k' == R8 -> bit-identical fea values
__global__ void __launch_bounds__(128) conv2_gemm_kernel(const float* __restrict__ b2) {
    extern __shared__ __align__(16) float cs[];
    float* inS = cs;                  // [2][32][68]
    float* wS  = cs + 2 * 32 * 68;    // [2][32][264]
    int n = blockIdx.x, tid = threadIdx.x;
    int tx = tid & 7, ty = tid >> 3;      // tx: spix-group (8 spix), ty: oc-group (16 oc)
    const float* xrow = g_xcol + (size_t)n * K2 * 64;

    unsigned long long acc2[8][8];
#pragma unroll
    for (int i = 0; i < 8; i++)
#pragma unroll
        for (int p = 0; p < 8; p++) acc2[i][p] = 0ull;

    auto issue = [&](int kt) {
        int st = kt & 1, k0 = kt * 32;
        for (int i = tid; i < 512; i += 128) {
            int r = i >> 4, seg = i & 15;
            cpasync16(s2u(&inS[(st * 32 + r) * 68 + seg * 4]),
                      xrow + (size_t)(k0 + r) * 64 + seg * 4);
        }
        for (int i = tid; i < 2048; i += 128) {
            int r = i >> 6, seg = i & 63;
            cpasync16(s2u(&wS[(st * 32 + r) * 264 + seg * 4]),
                      g_w2p + (size_t)(k0 + r) * 256 + seg * 4);
        }
        asm volatile("cp.async.commit_group;");
    };

    issue(0);
    for (int kt = 0; kt < 64; kt++) {
        if (kt + 1 < 64) {
            issue(kt + 1);
            asm volatile("cp.async.wait_group 1;");
        } else {
            asm volatile("cp.async.wait_group 0;");
        }
        __syncthreads();
        int st = kt & 1;
#pragma unroll
        for (int k = 0; k < 32; k++) {
            const float4 a0 = *(const float4*)&inS[(st * 32 + k) * 68 + tx * 8];
            const float4 a1 = *(const float4*)&inS[(st * 32 + k) * 68 + tx * 8 + 4];
            const ulonglong2* wp = (const ulonglong2*)&wS[(st * 32 + k) * 264 + ty * 16];
            ulonglong2 wa = wp[0], wb = wp[1], wc = wp[2], wd = wp[3];
            float av[8] = {a0.x, a0.y, a0.z, a0.w, a1.x, a1.y, a1.z, a1.w};
#pragma unroll
            for (int i = 0; i < 8; i++) {
                unsigned long long aw = pk2(av[i], av[i]);
                FMA2(acc2[i][0], aw, wa.x);  FMA2(acc2[i][1], aw, wa.y);
                FMA2(acc2[i][2], aw, wb.x);  FMA2(acc2[i][3], aw, wb.y);
                FMA2(acc2[i][4], aw, wc.x);  FMA2(acc2[i][5], aw, wc.y);
                FMA2(acc2[i][6], aw, wd.x);  FMA2(acc2[i][7], aw, wd.y);
            }
        }
        __syncthreads();
    }

    // fused epilogue: relu(acc+b2) -> feaT fp32 + feah/feal bf16 (row-major)
    float bias[16];
#pragma unroll
    for (int p = 0; p < 16; p++) bias[p] = __ldg(&b2[ty * 16 + p]);
#pragma unroll
    for (int i = 0; i < 8; i++) {
        size_t row = (size_t)n * 64 + tx * 8 + i;
        float v[16];
#pragma unroll
        for (int p = 0; p < 8; p++) {
            float2 t2 = upk2(acc2[i][p]);
            v[2 * p]     = fmaxf(t2.x + bias[2 * p],     0.f);
            v[2 * p + 1] = fmaxf(t2.y + bias[2 * p + 1], 0.f);
        }
        float* fT = &g_feaT[row * 256 + ty * 16];
#pragma unroll
        for (int q = 0; q < 4; q++)
            ((float4*)fT)[q] = make_float4(v[4 * q], v[4 * q + 1], v[4 * q + 2], v[4 * q + 3]);
        uint32_t hh[8], ll[8];
#pragma unroll
        for (int p = 0; p < 8; p++) {
            __nv_bfloat162 hp, lp;
            split2(v[2 * p],     hp.x, lp.x);
            split2(v[2 * p + 1], hp.y, lp.y);
            hh[p] = *(uint32_t*)&hp;
            ll[p] = *(uint32_t*)&lp;
        }
        uint4* ph = (uint4*)&g_feah[row * 256 + ty * 16];
        uint4* pl = (uint4*)&g_feal[row * 256 + ty * 16];
        ph[0] = make_uint4(hh[0], hh[1], hh[2], hh[3]);
        ph[1] = make_uint4(hh[4], hh[5], hh[6], hh[7]);
        pl[0] = make_uint4(ll[0], ll[1], ll[2], ll[3]);
        pl[1] = make_uint4(ll[4], ll[5], ll[6], ll[7]);
    }
}

// ---------------- prep: codes fp32 + split + norms + Kc (R8 verbatim) ---------
__global__ void prep_codes_kernel(const float* __restrict__ cb0, const float* __restrict__ cb1,
                                  const float* __restrict__ cb2, const int* __restrict__ idxp) {
    __shared__ float wsum[8];
    int j = blockIdx.x, d = threadIdx.x;
    int idx = *idxp;
    int Kc = (idx == 0) ? 512 : 1024;
    if (j == 0 && d == 0) g_Kc = Kc;
    float v = 0.f;
    if (j < Kc) {
        const float* cbh = (idx == 1) ? cb1 : cb2;
        v = (j < 512) ? cb0[j * 256 + d] : cbh[(j - 512) * 256 + d];
    }
    g_cbF[j * 256 + d] = v;
    split2(v, g_cbh[j * 256 + d], g_cbl[j * 256 + d]);
    float sq = v * v;
#pragma unroll
    for (int o = 16; o; o >>= 1) sq += __shfl_xor_sync(0xffffffffu, sq, o);
    if ((d & 31) == 0) wsum[d >> 5] = sq;
    __syncthreads();
    if (d == 0) {
        float t = 0.f;
        for (int w = 0; w < 8; w++) t += wsum[w];
        g_cn2[j] = t;
    }
}

// ---------------- VQ scores GEMM bf16x3 (R8 verbatim) -------------------------
__global__ void __launch_bounds__(256) scores_kernel() {
    constexpr int BM = 128, BN = 128, LDK = 40, K = DDIM;
    constexpr int BOFF = 2 * 2 * BM * LDK;
    if ((int)blockIdx.x * BN >= g_Kc) return;

    const __nv_bfloat16* Ag[2] = {g_feah, g_feal};
    const __nv_bfloat16* Bg[2] = {g_cbh, g_cbl};

    extern __shared__ __nv_bfloat16 sm[];
    const int tid = threadIdx.x;
    const int warp = tid >> 5, lane = tid & 31;
    const int wm = warp & 1, wn = warp >> 1;
    const size_t m0 = (size_t)blockIdx.y * BM;
    const int n0 = blockIdx.x * BN;

    float acc[4][4][4];
#pragma unroll
    for (int i = 0; i < 4; i++)
#pragma unroll
        for (int j = 0; j < 4; j++)
#pragma unroll
            for (int q = 0; q < 4; q++) acc[i][j][q] = 0.f;

    auto issue = [&](int kt) {
        int st = kt & 1;
        size_t kb = (size_t)kt * 32;
#pragma unroll
        for (int p = 0; p < 2; p++) {
            for (int i = tid; i < BM * 4; i += 256) {
                int r = i >> 2, c = (i & 3) * 8;
                cpasync16(s2u(&sm[((p * 2 + st) * BM + r) * LDK + c]),
                          Ag[p] + (m0 + r) * K + kb + c);
            }
            for (int i = tid; i < BN * 4; i += 256) {
                int r = i >> 2, c = (i & 3) * 8;
                cpasync16(s2u(&sm[BOFF + ((p * 2 + st) * BN + r) * LDK + c]),
                          Bg[p] + (size_t)(n0 + r) * K + kb + c);
            }
        }
        asm volatile("cp.async.commit_group;");
    };

    constexpr int NK = K / 32;
    issue(0);
    for (int kt = 0; kt < NK; kt++) {
        if (kt + 1 < NK) {
            issue(kt + 1);
            asm volatile("cp.async.wait_group 1;");
        } else {
            asm volatile("cp.async.wait_group 0;");
        }
        __syncthreads();
        int st = kt & 1;
#pragma unroll
        for (int ks = 0; ks < 2; ks++) {
            int arow = wm * 64 + (lane & 15);
            int acol = ks * 16 + (lane >> 4) * 8;
            int brow = wn * 32 + (lane & 7) + ((lane >> 4) << 3);
            int bcol = ks * 16 + ((lane >> 3) & 1) * 8;

            uint32_t a0[4][4], a1[4][4], b0[2][4], b1[2][4];
#pragma unroll
            for (int mi = 0; mi < 4; mi++) {
                ldsm4(a0[mi], s2u(&sm[((0 * 2 + st) * BM + arow + mi * 16) * LDK + acol]));
                ldsm4(a1[mi], s2u(&sm[((1 * 2 + st) * BM + arow + mi * 16) * LDK + acol]));
            }
#pragma unroll
            for (int g = 0; g < 2; g++) {
                ldsm4(b0[g], s2u(&sm[BOFF + ((0 * 2 + st) * BN + brow + g * 16) * LDK + bcol]));
                ldsm4(b1[g], s2u(&sm[BOFF + ((1 * 2 + st) * BN + brow + g * 16) * LDK + bcol]));
            }
#pragma unroll
            for (int mi = 0; mi < 4; mi++)
#pragma unroll
                for (int j = 0; j < 4; j++) {
                    int g = j >> 1, o = (j & 1) * 2;
                    mma16816(acc[mi][j], a0[mi], &b0[g][o]);
                    mma16816(acc[mi][j], a0[mi], &b1[g][o]);
                    mma16816(acc[mi][j], a1[mi], &b0[g][o]);
                }
        }
        __syncthreads();
    }

#pragma unroll
    for (int mi = 0; mi < 4; mi++)
#pragma unroll
        for (int j = 0; j < 4; j++) {
            size_t row = m0 + wm * 64 + mi * 16 + (lane >> 2);
            int col = n0 + wn * 32 + j * 8 + (lane & 3) * 2;
            float* c = acc[mi][j];
#pragma unroll
            for (int half = 0; half < 2; half++) {
                size_t r = row + half * 8;
                float2 o;
                o.x = c[half * 2 + 0] - 0.5f * __ldg(&g_cn2[col]);
                o.y = c[half * 2 + 1] - 0.5f * __ldg(&g_cn2[col + 1]);
                *reinterpret_cast<float2*>(&g_scores[r * KMAX + col]) = o;
            }
        }
}

// ---------------- argmax top-2 (coalesced f4 scan) + exact refine (R8 arith) --
__global__ void argmax_refine_kernel() {
    int row = (blockIdx.x * 256 + threadIdx.x) >> 5;
    int lane = threadIdx.x & 31;
    int Kc = g_Kc;
    const float4* sc4 = (const float4*)(g_scores + (size_t)row * KMAX);

    float s1 = -3.4e38f, s2c = -3.4e38f;
    int i1 = -1, i2 = -1;
    auto upd = [&](float v, int c) {
        if (c == i1 || c == i2 || c < 0) return;
        if (v > s1 || (v == s1 && c < i1)) { s2c = s1; i2 = i1; s1 = v; i1 = c; }
        else if (v > s2c || (v == s2c && c < i2)) { s2c = v; i2 = c; }
    };
    int K4 = Kc >> 2;
    for (int c4 = lane; c4 < K4; c4 += 32) {
        float4 v = sc4[c4];
        int c = c4 * 4;
        upd(v.x, c); upd(v.y, c + 1); upd(v.z, c + 2); upd(v.w, c + 3);
    }
#pragma unroll
    for (int off = 16; off; off >>= 1) {
        float os1 = __shfl_xor_sync(0xffffffffu, s1, off);
        int   oi1 = __shfl_xor_sync(0xffffffffu, i1, off);
        float os2 = __shfl_xor_sync(0xffffffffu, s2c, off);
        int   oi2 = __shfl_xor_sync(0xffffffffu, i2, off);
        upd(os1, oi1);
        upd(os2, oi2);
    }

    // exact fp32 refine — KEEP R8 arithmetic order exactly
    const float* f  = g_feaT + (size_t)row * DDIM;
    const float* c0 = g_cbF + (size_t)i1 * DDIM;
    const float* c1 = g_cbF + (size_t)i2 * DDIM;
    float d0 = 0.f, d1 = 0.f;
    for (int k = lane; k < DDIM; k += 32) {
        float fv = f[k];
        d0 += fv * c0[k];
        d1 += fv * c1[k];
    }
#pragma unroll
    for (int off = 16; off; off >>= 1) {
        d0 += __shfl_xor_sync(0xffffffffu, d0, off);
        d1 += __shfl_xor_sync(0xffffffffu, d1, off);
    }
    float e0 = d0 - 0.5f * g_cn2[i1];
    float e1 = d1 - 0.5f * g_cn2[i2];
    int best = (e1 > e0 || (e1 == e0 && i2 < i1)) ? i2 : i1;
    if (lane == 0) g_bi[row] = best;
}

// ---------------- gather: float4-vectorized -----------------------------------
__global__ void gather_kernel(const float* __restrict__ cb0, const float* __restrict__ cb1,
                              const float* __restrict__ cb2, const int* __restrict__ idxp) {
    __shared__ int sbi[64];
    __shared__ float wsum[8];
    int n = blockIdx.x, tid = threadIdx.x;
    int idx = *idxp;
    const float* cbh = (idx == 1) ? cb1 : cb2;
    if (tid < 64) {
        int b = g_bi[n * 64 + tid];
        sbi[tid] = b;
        atomicAdd(&g_counts[b], 1);
    }
    __syncthreads();
    float local = 0.f;
    for (int t = tid; t < 4096; t += 256) {
        int srow = t >> 6, oc4 = (t & 63) * 4;
        int b = sbi[srow];
        const float* cp = (b < 512) ? (cb0 + (size_t)b * 256) : (cbh + (size_t)(b - 512) * 256);
        float4 q4 = *(const float4*)&cp[oc4];
        size_t r = ((size_t)n * 64 + srow) * 256 + oc4;
        float4 f4 = *(const float4*)&g_feaT[r];
        float d0 = q4.x - f4.x, d1 = q4.y - f4.y, d2 = q4.z - f4.z, d3 = q4.w - f4.w;
        local += d0 * d0 + d1 * d1 + d2 * d2 + d3 * d3;
        __nv_bfloat162 h01, l01, h23, l23;
        split2(q4.x, h01.x, l01.x); split2(q4.y, h01.y, l01.y);
        split2(q4.z, h23.x, l23.x); split2(q4.w, h23.y, l23.y);
        *(uint2*)&g_qh[r] = make_uint2(*(uint32_t*)&h01, *(uint32_t*)&h23);
        *(uint2*)&g_ql[r] = make_uint2(*(uint32_t*)&l01, *(uint32_t*)&l23);
    }
#pragma unroll
    for (int o = 16; o; o >>= 1) local += __shfl_xor_sync(0xffffffffu, local, o);
    if ((tid & 31) == 0) wsum[tid >> 5] = local;
    __syncthreads();
    if (tid == 0) {
        float t = 0.f;
        for (int w = 0; w < 8; w++) t += wsum[w];
        atomicAdd(&g_lossSum, t);
    }
}

// ---------------- prep: fc1 weight permute + split (R8 verbatim) --------------
__global__ void prep_f1w_kernel(const float* __restrict__ f1w) {
    int gid = blockIdx.x * 256 + threadIdx.x;
    int h = gid >> 14, kp = gid & 16383;
    int s = kp >> 8, oc = kp & 255;
    float v = f1w[(size_t)h * CH + oc * 64 + s];
    split2(v, g_f1wh[gid], g_f1wl[gid]);
}

// ---------------- fc1 TC GEMM (R8 verbatim) ----------------
__global__ void __launch_bounds__(256) fc1_tc_kernel(const float* __restrict__ f1b) {
    constexpr int BM = 128, BN = 64, LDK = 40, K = CH;
    constexpr int BOFF = 2 * 2 * BM * LDK;
    const __nv_bfloat16* Ag[2] = {g_qh, g_ql};
    const __nv_bfloat16* Bg[2] = {g_f1wh, g_f1wl};
    extern __shared__ __nv_bfloat16 sm[];
    const int tid = threadIdx.x;
    const int warp = tid >> 5, lane = tid & 31;
    const int wm = warp & 1, wn = warp >> 1;
    const size_t m0 = (size_t)blockIdx.y * BM;
    const int n0 = blockIdx.x * BN;

    float acc[4][2][4];
#pragma unroll
    for (int i = 0; i < 4; i++)
#pragma unroll
        for (int j = 0; j < 2; j++)
#pragma unroll
            for (int q = 0; q < 4; q++) acc[i][j][q] = 0.f;

    auto issue = [&](int kt) {
        int st = kt & 1;
        size_t kb = (size_t)kt * 32;
#pragma unroll
        for (int p = 0; p < 2; p++) {
            for (int i = tid; i < BM * 4; i += 256) {
                int r = i >> 2, c = (i & 3) * 8;
                cpasync16(s2u(&sm[((p * 2 + st) * BM + r) * LDK + c]),
                          Ag[p] + (m0 + r) * K + kb + c);
            }
            for (int i = tid; i < BN * 4; i += 256) {
                int r = i >> 2, c = (i & 3) * 8;
                cpasync16(s2u(&sm[BOFF + ((p * 2 + st) * BN + r) * LDK + c]),
                          Bg[p] + (size_t)(n0 + r) * K + kb + c);
            }
        }
        asm volatile("cp.async.commit_group;");
    };

    constexpr int NK = K / 32;
    issue(0);
    for (int kt = 0; kt < NK; kt++) {
        if (kt + 1 < NK) {
            issue(kt + 1);
            asm volatile("cp.async.wait_group 1;");
        } else {
            asm volatile("cp.async.wait_group 0;");
        }
        __syncthreads();
        int st = kt & 1;
#pragma unroll
        for (int ks = 0; ks < 2; ks++) {
            int arow = wm * 64 + (lane & 15);
            int acol = ks * 16 + (lane >> 4) * 8;
            int brow = wn * 16 + (lane & 7) + ((lane >> 4) << 3);
            int bcol = ks * 16 + ((lane >> 3) & 1) * 8;
            uint32_t a0[4][4], a1[4][4], b0[4], b1[4];
#pragma unroll
            for (int mi = 0; mi < 4; mi++) {
                ldsm4(a0[mi], s2u(&sm[((0 * 2 + st) * BM + arow + mi * 16) * LDK + acol]));
                ldsm4(a1[mi], s2u(&sm[((1 * 2 + st) * BM + arow + mi * 16) * LDK + acol]));
            }
            ldsm4(b0, s2u(&sm[BOFF + ((0 * 2 + st) * BN + brow) * LDK + bcol]));
            ldsm4(b1, s2u(&sm[BOFF + ((1 * 2 + st) * BN + brow) * LDK + bcol]));
#pragma unroll
            for (int mi = 0; mi < 4; mi++)
#pragma unroll
                for (int j = 0; j < 2; j++) {
                    mma16816(acc[mi][j], a0[mi], &b0[j * 2]);
                    mma16816(acc[mi][j], a0[mi], &b1[j * 2]);
                    mma16816(acc[mi][j], a1[mi], &b0[j * 2]);
                }
        }
        __syncthreads();
    }

#pragma unroll
    for (int mi = 0; mi < 4; mi++)
#pragma unroll
        for (int j = 0; j < 2; j++) {
            size_t row = m0 + wm * 64 + mi * 16 + (lane >> 2);
            int col = n0 + wn * 16 + j * 8 + (lane & 3) * 2;
            float* c = acc[mi][j];
#pragma unroll
            for (int half = 0; half < 2; half++) {
                size_t r = row + half * 8;
                float a0v = c[half * 2 + 0] + __ldg(&f1b[col]);
                float a1v = c[half * 2 + 1] + __ldg(&f1b[col + 1]);
                float2 o;
                o.x = 0.5f * a0v * (1.f + erff(a0v * 0.70710678118654752f));
                o.y = 0.5f * a1v * (1.f + erff(a1v * 0.70710678118654752f));
                *reinterpret_cast<float2*>(&g_h1[r * HID + col]) = o;
            }
        }
}

// ---------------- fc2 (R1 verbatim) ----------------
__global__ void fc2_kernel(const float* __restrict__ w, const float* __restrict__ b,
                           float* __restrict__ out) {
    int gwarp = (blockIdx.x * 256 + threadIdx.x) >> 5;
    int lane = threadIdx.x & 31;
    if (gwarp >= NB) return;
    float acc[10];
#pragma unroll
    for (int o = 0; o < 10; o++) acc[o] = 0.f;
    const float* hrow = g_h1 + (size_t)gwarp * HID;
    for (int k = lane; k < HID; k += 32) {
        float h = hrow[k];
#pragma unroll
        for (int o = 0; o < 10; o++) acc[o] += h * w[o * HID + k];
    }
#pragma unroll
    for (int o = 0; o < 10; o++)
#pragma unroll
        for (int off = 16; off; off >>= 1) acc[o] += __shfl_xor_sync(0xffffffffu, acc[o], off);
    if (lane == 0) {
#pragma unroll
        for (int o = 0; o < 10; o++) out[(size_t)gwarp * 10 + o] = acc[o] + b[o];
    }
}

// ---------------- finalize (R1 verbatim) ----------------
__global__ void finalize_kernel(float* __restrict__ out) {
    __shared__ float wsum[8];
    int tid = threadIdx.x;
    float local = 0.f;
    for (int k = tid; k < KMAX; k += 256) {
        float p = (float)g_counts[k] * (1.0f / 131072.0f);
        local += p * logf(p + 1e-10f);
    }
#pragma unroll
    for (int o = 16; o; o >>= 1) local += __shfl_xor_sync(0xffffffffu, local, o);
    if ((tid & 31) == 0) wsum[tid >> 5] = local;
    __syncthreads();
    if (tid == 0) {
        float t = 0.f;
        for (int w = 0; w < 8; w++) t += wsum[w];
        out[20480] = 1.25f * g_lossSum * (1.0f / 33554432.0f);
        out[20481] = expf(-t);
    }
}

// ---------------- launch ----------------
extern "C" void kernel_launch(void* const* d_in, const int* in_sizes, int n_in,
                              void* d_out, int out_size) {
    const float* x    = (const float*)d_in[0];
    const int*   idxp = (const int*)  d_in[1];
    const float* w1   = (const float*)d_in[2];
    const float* b1   = (const float*)d_in[3];
    const float* w2   = (const float*)d_in[4];
    const float* b2   = (const float*)d_in[5];
    const float* cb0  = (const float*)d_in[6];
    const float* cb1  = (const float*)d_in[7];
    const float* cb2  = (const float*)d_in[8];
    const float* f1w  = (const float*)d_in[9];
    const float* f1b  = (const float*)d_in[10];
    const float* f2w  = (const float*)d_in[11];
    const float* f2b  = (const float*)d_in[12];
    float* out = (float*)d_out;

    constexpr int SM1 = 3072 * 4 + 6144 * 8 + 128 * 4;            // 61952
    constexpr int SMC = (2 * 32 * 68 + 2 * 32 * 264) * 4;         // 84992
    constexpr int SMS = (2 * 2 * 128 + 2 * 2 * 128) * 40 * 2;     // 81920
    constexpr int SMF = (2 * 2 * 128 + 2 * 2 * 64)  * 40 * 2;     // 61440
    cudaFuncSetAttribute(conv1_kernel,      cudaFuncAttributeMaxDynamicSharedMemorySize, SM1);
    cudaFuncSetAttribute(conv2_gemm_kernel, cudaFuncAttributeMaxDynamicSharedMemorySize, SMC);
    cudaFuncSetAttribute(scores_kernel,     cudaFuncAttributeMaxDynamicSharedMemorySize, SMS);
    cudaFuncSetAttribute(fc1_tc_kernel,     cudaFuncAttributeMaxDynamicSharedMemorySize, SMF);

    zero_stats_kernel<<<1, 1024>>>();
    prep_f1w_kernel<<<32768, 256>>>(f1w);
    prep_w2p_kernel<<<2048, 256>>>(w2);
    prep_codes_kernel<<<1024, 256>>>(cb0, cb1, cb2, idxp);
    conv1_kernel<<<NB, 128, SM1>>>(x, w1, b1);
    im2col_kernel<<<dim3(16, NB), 256>>>();
    conv2_gemm_kernel<<<NB, 128, SMC>>>(b2);
    scores_kernel<<<dim3(8, 1024), 256, SMS>>>();
    argmax_refine_kernel<<<NROWS / 8, 256>>>();
    gather_kernel<<<NB, 256>>>(cb0, cb1, cb2, idxp);
    fc1_tc_kernel<<<dim3(8, 16), 256, SMF>>>(f1b);
    fc2_kernel<<<NB / 8, 256>>>(f2w, f2b, out);
    finalize_kernel<<<1, 256>>>(out);
}

// round 10
// speedup vs baseline: 1.0548x; 1.0548x over previous
#include <cuda_runtime.h>
#include <cuda_bf16.h>
#include <math.h>
#include <stdint.h>

// ---------------- problem constants ----------------
#define NB    2048
#define NPIX1 256
#define C1    128
#define SPIX  64
#define NROWS (NB*SPIX)
#define DDIM  256
#define KMAX  1024
#define CH    16384
#define HID   512
#define K2    2048

// ---------------- scratch ----------------
__device__ float         g_relu1[(size_t)NB * C1 * NPIX1];
__device__ float         g_xcol [(size_t)NB * K2 * 64];      // [n][k'][64 spix]
__device__ float         g_w2p  [K2 * 256];                  // [k'][oc]
__device__ float         g_feaT [(size_t)NROWS * DDIM];      // [row][oc] fp32
__device__ __nv_bfloat16 g_feah[(size_t)NROWS * DDIM], g_feal[(size_t)NROWS * DDIM];
__device__ __nv_bfloat16 g_cbh[KMAX * DDIM], g_cbl[KMAX * DDIM];
__device__ float         g_cbF[KMAX * DDIM];
__device__ float         g_cn2[KMAX];
__device__ unsigned long long g_cand[(size_t)NROWS * 16];    // [row][blk*2+{0,1}]
__device__ int           g_bi[NROWS];
__device__ __nv_bfloat16 g_qh[(size_t)NB * CH], g_ql[(size_t)NB * CH];
__device__ __nv_bfloat16 g_f1wh[(size_t)HID * CH], g_f1wl[(size_t)HID * CH];
__device__ float         g_h1[(size_t)NB * HID];
__device__ int           g_counts[KMAX];
__device__ float         g_lossSum;
__device__ int           g_Kc;

// ---------------- helpers ----------------
__device__ __forceinline__ uint32_t s2u(const void* p) {
    return (uint32_t)__cvta_generic_to_shared(p);
}
__device__ __forceinline__ void cpasync16(uint32_t s, const void* g) {
    asm volatile("cp.async.cg.shared.global [%0], [%1], 16;" :: "r"(s), "l"(g));
}
__device__ __forceinline__ void ldsm4(uint32_t* r, uint32_t s) {
    asm volatile("ldmatrix.sync.aligned.m8n8.x4.shared.b16 {%0,%1,%2,%3}, [%4];"
                 : "=r"(r[0]), "=r"(r[1]), "=r"(r[2]), "=r"(r[3]) : "r"(s));
}
__device__ __forceinline__ void mma16816(float* c, const uint32_t* a, const uint32_t* b) {
    asm volatile("mma.sync.aligned.m16n8k16.row.col.f32.bf16.bf16.f32 "
                 "{%0,%1,%2,%3}, {%4,%5,%6,%7}, {%8,%9}, {%0,%1,%2,%3};"
                 : "+f"(c[0]), "+f"(c[1]), "+f"(c[2]), "+f"(c[3])
                 : "r"(a[0]), "r"(a[1]), "r"(a[2]), "r"(a[3]), "r"(b[0]), "r"(b[1]));
}
__device__ __forceinline__ void split2(float v, __nv_bfloat16& h, __nv_bfloat16& l) {
    h = __float2bfloat16(v);
    l = __float2bfloat16(v - __bfloat162float(h));
}
__device__ __forceinline__ unsigned long long pk2(float x, float y) {
    unsigned long long r;
    asm("mov.b64 %0, {%1, %2};" : "=l"(r) : "f"(x), "f"(y));
    return r;
}
__device__ __forceinline__ float2 upk2(unsigned long long v) {
    float2 f;
    asm("mov.b64 {%0, %1}, %2;" : "=f"(f.x), "=f"(f.y) : "l"(v));
    return f;
}
#define FMA2(d, a, b) asm("fma.rn.f32x2 %0, %1, %2, %0;" : "+l"(d) : "l"(a), "l"(b))

// pack (score, col) so that u64 ordering == (score asc, then col desc);
// larger packed value == better candidate (higher score, tie -> smaller col)
__device__ __forceinline__ unsigned long long packsc(float s, int c) {
    uint32_t b = __float_as_uint(s);
    b = ((int32_t)b < 0) ? ~b : (b | 0x80000000u);
    return ((unsigned long long)b << 32) | (uint32_t)(KMAX - 1 - c);
}
__device__ __forceinline__ void unpacksc(unsigned long long p, float& s, int& c) {
    uint32_t hb = (uint32_t)(p >> 32);
    uint32_t ob = (hb & 0x80000000u) ? (hb ^ 0x80000000u) : ~hb;
    s = __uint_as_float(ob);
    c = (KMAX - 1) - (int)(p & 0xffffffffu);
}

// ---------------- zero stats ----------------
__global__ void zero_stats_kernel() {
    int t = threadIdx.x;
    if (t < KMAX) g_counts[t] = 0;
    if (t == 0)   g_lossSum = 0.f;
}

// ---------------- conv1 (R9 verbatim: FFMA2, 2 pixels/thread) ------------------
__global__ void __launch_bounds__(128) conv1_kernel(const float* __restrict__ x,
                                                    const float* __restrict__ w1,
                                                    const float* __restrict__ b1) {
    extern __shared__ float s1[];
    float* sIn = s1;
    unsigned long long* sW2 = (unsigned long long*)(s1 + 3072);
    float* sB = (float*)(sW2 + 6144);
    int n = blockIdx.x, tid = threadIdx.x;
    for (int i = tid; i < 3072; i += 128) sIn[i] = x[(size_t)n * 3072 + i];
    for (int i = tid; i < 6144; i += 128) { float w = w1[i]; sW2[i] = pk2(w, w); }
    if (tid < 128) sB[tid] = b1[tid];
    __syncthreads();

    int p0 = tid * 2;
    int oh = p0 >> 4, ow0 = p0 & 15, ow1 = ow0 + 1;
    unsigned long long a2[48];
#pragma unroll
    for (int ci = 0; ci < 3; ci++)
#pragma unroll
        for (int kh = 0; kh < 4; kh++)
#pragma unroll
            for (int kw = 0; kw < 4; kw++) {
                int ih = 2 * oh - 1 + kh;
                int iw0 = 2 * ow0 - 1 + kw, iw1 = 2 * ow1 - 1 + kw;
                bool rv = (ih >= 0 && ih < 32);
                float v0 = (rv && iw0 >= 0 && iw0 < 32) ? sIn[ci * 1024 + ih * 32 + iw0] : 0.f;
                float v1 = (rv && iw1 < 32) ? sIn[ci * 1024 + ih * 32 + iw1] : 0.f;
                a2[ci * 16 + kh * 4 + kw] = pk2(v0, v1);
            }

    float* outp = g_relu1 + (size_t)n * (C1 * NPIX1);
    for (int ch = 0; ch < 4; ch++) {
        unsigned long long acc2[32];
#pragma unroll
        for (int o = 0; o < 32; o++) { float b = sB[ch * 32 + o]; acc2[o] = pk2(b, b); }
#pragma unroll
        for (int t = 0; t < 48; t++)
#pragma unroll
            for (int o = 0; o < 32; o++)
                FMA2(acc2[o], a2[t], sW2[(ch * 32 + o) * 48 + t]);
#pragma unroll
        for (int o = 0; o < 32; o++) {
            float2 v = upk2(acc2[o]);
            float2 st = {fmaxf(v.x, 0.f), fmaxf(v.y, 0.f)};
            *(float2*)&outp[(size_t)(ch * 32 + o) * 256 + p0] = st;
        }
    }
}

// ---------------- im2col fp32 (R8 verbatim) ----------------
__global__ void im2col_kernel() {
    int kcblk = blockIdx.x;
    int n     = blockIdx.y;
    int tid = threadIdx.x;
    for (int t = tid; t < 8192; t += 256) {
        int kl = t >> 6, s = t & 63;
        int tap = kl >> 3, ciL = kl & 7;
        int ci = kcblk * 8 + ciL;
        int kh = tap >> 2, kw = tap & 3;
        int oh = s >> 3, ow = s & 7;
        int ih = 2 * oh - 1 + kh, iw = 2 * ow - 1 + kw;
        float v = 0.f;
        if (ih >= 0 && ih < 16 && iw >= 0 && iw < 16)
            v = g_relu1[((size_t)n * 128 + ci) * 256 + ih * 16 + iw];
        g_xcol[(((size_t)n * 16 + kcblk) * 128 + kl) * 64 + s] = v;
    }
}

// ---------------- prep: permuted w2p[k'][oc] (R8 verbatim) ----------------
__global__ void prep_w2p_kernel(const float* __restrict__ w2) {
    int gid = blockIdx.x * 256 + threadIdx.x;
    int oc = gid & 255, kp = gid >> 8;
    int kcblk = kp >> 7, r = kp & 127;
    int tap = r >> 3, ciL = r & 7;
    int gk = (kcblk * 8 + ciL) * 16 + tap;
    g_w2p[gid] = w2[(size_t)oc * 2048 + gk];
}

// ---------------- conv2 GEMM: R8 256-thread mainloop + fused epilogue ---------
__global__ void __launch_bounds__(256, 2) conv2_gemm_kernel(const float* __restrict__ b2) {
    extern __shared__ __align__(16) float cs[];
    float* inS = cs;                  // [2][32][68]
    float* wS  = cs + 2 * 32 * 68;    // [2][32][264]
    int n = blockIdx.x, tid = threadIdx.x;
    int tx = tid & 15, ty = tid >> 4;     // tx: 4-spix group, ty: 16-oc group
    const float* xrow = g_xcol + (size_t)n * K2 * 64;

    unsigned long long acc2[4][8];
#pragma unroll
    for (int i = 0; i < 4; i++)
#pragma unroll
        for (int p = 0; p < 8; p++) acc2[i][p] = 0ull;

    auto issue = [&](int kt) {
        int st = kt & 1, k0 = kt * 32;
        for (int i = tid; i < 512; i += 256) {
            int r = i >> 4, seg = i & 15;
            cpasync16(s2u(&inS[(st * 32 + r) * 68 + seg * 4]),
                      xrow + (size_t)(k0 + r) * 64 + seg * 4);
        }
        for (int i = tid; i < 2048; i += 256) {
            int r = i >> 6, seg = i & 63;
            cpasync16(s2u(&wS[(st * 32 + r) * 264 + seg * 4]),
                      g_w2p + (size_t)(k0 + r) * 256 + seg * 4);
        }
        asm volatile("cp.async.commit_group;");
    };

    issue(0);
    for (int kt = 0; kt < 64; kt++) {
        if (kt + 1 < 64) {
            issue(kt + 1);
            asm volatile("cp.async.wait_group 1;");
        } else {
            asm volatile("cp.async.wait_group 0;");
        }
        __syncthreads();
        int st = kt & 1;
#pragma unroll
        for (int k = 0; k < 32; k++) {
            float4 a4 = *(const float4*)&inS[(st * 32 + k) * 68 + tx * 4];
            const ulonglong2* wp = (const ulonglong2*)&wS[(st * 32 + k) * 264 + ty * 16];
            ulonglong2 wa = wp[0], wb = wp[1], wc = wp[2], wd = wp[3];
            unsigned long long aw[4] = {pk2(a4.x, a4.x), pk2(a4.y, a4.y),
                                        pk2(a4.z, a4.z), pk2(a4.w, a4.w)};
#pragma unroll
            for (int i = 0; i < 4; i++) {
                FMA2(acc2[i][0], aw[i], wa.x);  FMA2(acc2[i][1], aw[i], wa.y);
                FMA2(acc2[i][2], aw[i], wb.x);  FMA2(acc2[i][3], aw[i], wb.y);
                FMA2(acc2[i][4], aw[i], wc.x);  FMA2(acc2[i][5], aw[i], wc.y);
                FMA2(acc2[i][6], aw[i], wd.x);  FMA2(acc2[i][7], aw[i], wd.y);
            }
        }
        __syncthreads();
    }

    // fused epilogue: relu(acc+b2) -> feaT fp32 + feah/feal bf16 (row-major)
    float bias[16];
#pragma unroll
    for (int p = 0; p < 16; p++) bias[p] = __ldg(&b2[ty * 16 + p]);
#pragma unroll
    for (int i = 0; i < 4; i++) {
        size_t row = (size_t)n * 64 + tx * 4 + i;
        float v[16];
#pragma unroll
        for (int p = 0; p < 8; p++) {
            float2 t2 = upk2(acc2[i][p]);
            v[2 * p]     = fmaxf(t2.x + bias[2 * p],     0.f);
            v[2 * p + 1] = fmaxf(t2.y + bias[2 * p + 1], 0.f);
        }
        float* fT = &g_feaT[row * 256 + ty * 16];
#pragma unroll
        for (int q = 0; q < 4; q++)
            ((float4*)fT)[q] = make_float4(v[4 * q], v[4 * q + 1], v[4 * q + 2], v[4 * q + 3]);
        uint32_t hh[8], ll[8];
#pragma unroll
        for (int p = 0; p < 8; p++) {
            __nv_bfloat162 hp, lp;
            split2(v[2 * p],     hp.x, lp.x);
            split2(v[2 * p + 1], hp.y, lp.y);
            hh[p] = *(uint32_t*)&hp;
            ll[p] = *(uint32_t*)&lp;
        }
        uint4* ph = (uint4*)&g_feah[row * 256 + ty * 16];
        uint4* pl = (uint4*)&g_feal[row * 256 + ty * 16];
        ph[0] = make_uint4(hh[0], hh[1], hh[2], hh[3]);
        ph[1] = make_uint4(hh[4], hh[5], hh[6], hh[7]);
        pl[0] = make_uint4(ll[0], ll[1], ll[2], ll[3]);
        pl[1] = make_uint4(ll[4], ll[5], ll[6], ll[7]);
    }
}

// ---------------- prep: codes fp32 + split + norms + Kc (R8 verbatim) ---------
__global__ void prep_codes_kernel(const float* __restrict__ cb0, const float* __restrict__ cb1,
                                  const float* __restrict__ cb2, const int* __restrict__ idxp) {
    __shared__ float wsum[8];
    int j = blockIdx.x, d = threadIdx.x;
    int idx = *idxp;
    int Kc = (idx == 0) ? 512 : 1024;
    if (j == 0 && d == 0) g_Kc = Kc;
    float v = 0.f;
    if (j < Kc) {
        const float* cbh = (idx == 1) ? cb1 : cb2;
        v = (j < 512) ? cb0[j * 256 + d] : cbh[(j - 512) * 256 + d];
    }
    g_cbF[j * 256 + d] = v;
    split2(v, g_cbh[j * 256 + d], g_cbl[j * 256 + d]);
    float sq = v * v;
#pragma unroll
    for (int o = 16; o; o >>= 1) sq += __shfl_xor_sync(0xffffffffu, sq, o);
    if ((d & 31) == 0) wsum[d >> 5] = sq;
    __syncthreads();
    if (d == 0) {
        float t = 0.f;
        for (int w = 0; w < 8; w++) t += wsum[w];
        g_cn2[j] = t;
    }
}

// ---------------- VQ scores GEMM bf16x3 + fused per-tile top-2 ----------------
__global__ void __launch_bounds__(256) scores_kernel() {
    constexpr int BM = 128, BN = 128, LDK = 40, K = DDIM;
    constexpr int BOFF = 2 * 2 * BM * LDK;
    if ((int)blockIdx.x * BN >= g_Kc) return;

    const __nv_bfloat16* Ag[2] = {g_feah, g_feal};
    const __nv_bfloat16* Bg[2] = {g_cbh, g_cbl};

    extern __shared__ __nv_bfloat16 sm[];
    const int tid = threadIdx.x;
    const int warp = tid >> 5, lane = tid & 31;
    const int wm = warp & 1, wn = warp >> 1;
    const size_t m0 = (size_t)blockIdx.y * BM;
    const int n0 = blockIdx.x * BN;

    float acc[4][4][4];
#pragma unroll
    for (int i = 0; i < 4; i++)
#pragma unroll
        for (int j = 0; j < 4; j++)
#pragma unroll
            for (int q = 0; q < 4; q++) acc[i][j][q] = 0.f;

    auto issue = [&](int kt) {
        int st = kt & 1;
        size_t kb = (size_t)kt * 32;
#pragma unroll
        for (int p = 0; p < 2; p++) {
            for (int i = tid; i < BM * 4; i += 256) {
                int r = i >> 2, c = (i & 3) * 8;
                cpasync16(s2u(&sm[((p * 2 + st) * BM + r) * LDK + c]),
                          Ag[p] + (m0 + r) * K + kb + c);
            }
            for (int i = tid; i < BN * 4; i += 256) {
                int r = i >> 2, c = (i & 3) * 8;
                cpasync16(s2u(&sm[BOFF + ((p * 2 + st) * BN + r) * LDK + c]),
                          Bg[p] + (size_t)(n0 + r) * K + kb + c);
            }
        }
        asm volatile("cp.async.commit_group;");
    };

    constexpr int NK = K / 32;
    issue(0);
    for (int kt = 0; kt < NK; kt++) {
        if (kt + 1 < NK) {
            issue(kt + 1);
            asm volatile("cp.async.wait_group 1;");
        } else {
            asm volatile("cp.async.wait_group 0;");
        }
        __syncthreads();
        int st = kt & 1;
#pragma unroll
        for (int ks = 0; ks < 2; ks++) {
            int arow = wm * 64 + (lane & 15);
            int acol = ks * 16 + (lane >> 4) * 8;
            int brow = wn * 32 + (lane & 7) + ((lane >> 4) << 3);
            int bcol = ks * 16 + ((lane >> 3) & 1) * 8;

            uint32_t a0[4][4], a1[4][4], b0[2][4], b1[2][4];
#pragma unroll
            for (int mi = 0; mi < 4; mi++) {
                ldsm4(a0[mi], s2u(&sm[((0 * 2 + st) * BM + arow + mi * 16) * LDK + acol]));
                ldsm4(a1[mi], s2u(&sm[((1 * 2 + st) * BM + arow + mi * 16) * LDK + acol]));
            }
#pragma unroll
            for (int g = 0; g < 2; g++) {
                ldsm4(b0[g], s2u(&sm[BOFF + ((0 * 2 + st) * BN + brow + g * 16) * LDK + bcol]));
                ldsm4(b1[g], s2u(&sm[BOFF + ((1 * 2 + st) * BN + brow + g * 16) * LDK + bcol]));
            }
#pragma unroll
            for (int mi = 0; mi < 4; mi++)
#pragma unroll
                for (int j = 0; j < 4; j++) {
                    int g = j >> 1, o = (j & 1) * 2;
                    mma16816(acc[mi][j], a0[mi], &b0[g][o]);
                    mma16816(acc[mi][j], a0[mi], &b1[g][o]);
                    mma16816(acc[mi][j], a1[mi], &b0[g][o]);
                }
        }
        __syncthreads();
    }

    // ---- fused top-2 epilogue ----
    // per thread: 8 rows (mi x half) x 8 cols (j x 2). reduce to per-row top-2,
    // stage in smem, then 128 threads scan 16 slots/row -> global candidates.
    unsigned long long* scand = (unsigned long long*)sm;   // [128 rows][16 slots][2]
    __syncthreads();   // all smem reads of GEMM tiles done
#pragma unroll
    for (int mi = 0; mi < 4; mi++)
#pragma unroll
        for (int half = 0; half < 2; half++) {
            int crow = wm * 64 + mi * 16 + (lane >> 2) + half * 8;
            unsigned long long p1 = 0ull, p2 = 0ull;
#pragma unroll
            for (int j = 0; j < 4; j++) {
                int col = n0 + wn * 32 + j * 8 + (lane & 3) * 2;
                float s0 = acc[mi][j][half * 2 + 0] - 0.5f * __ldg(&g_cn2[col]);
                float s1v = acc[mi][j][half * 2 + 1] - 0.5f * __ldg(&g_cn2[col + 1]);
                unsigned long long pa = packsc(s0, col);
                unsigned long long pb = packsc(s1v, col + 1);
                if (pa > p1) { p2 = p1; p1 = pa; } else if (pa > p2) p2 = pa;
                if (pb > p1) { p2 = p1; p1 = pb; } else if (pb > p2) p2 = pb;
            }
            int slot = wn * 4 + (lane & 3);
            scand[(crow * 16 + slot) * 2 + 0] = p1;
            scand[(crow * 16 + slot) * 2 + 1] = p2;
        }
    __syncthreads();
    if (tid < 128) {
        unsigned long long p1 = 0ull, p2 = 0ull;
#pragma unroll
        for (int s = 0; s < 32; s++) {
            unsigned long long p = scand[tid * 32 + s];
            if (p > p1) { p2 = p1; p1 = p; } else if (p > p2) p2 = p;
        }
        size_t row = m0 + tid;
        g_cand[row * 16 + blockIdx.x * 2 + 0] = p1;
        g_cand[row * 16 + blockIdx.x * 2 + 1] = p2;
    }
}

// ---------------- refine: merge candidates + exact fp32 re-score (R8 arith) ---
__global__ void refine_kernel() {
    int row = (blockIdx.x * 256 + threadIdx.x) >> 5;
    int lane = threadIdx.x & 31;
    int nblk = g_Kc >> 7;   // 4 or 8

    float s1 = -3.4e38f, s2c = -3.4e38f;
    int i1 = -1, i2 = -1;
    auto upd = [&](float v, int c) {
        if (c == i1 || c == i2 || c < 0) return;
        if (v > s1 || (v == s1 && c < i1)) { s2c = s1; i2 = i1; s1 = v; i1 = c; }
        else if (v > s2c || (v == s2c && c < i2)) { s2c = v; i2 = c; }
    };
    if (lane < 2 * nblk) {
        float v; int c;
        unpacksc(g_cand[(size_t)row * 16 + lane], v, c);
        upd(v, c);
    }
#pragma unroll
    for (int off = 16; off; off >>= 1) {
        float os1 = __shfl_xor_sync(0xffffffffu, s1, off);
        int   oi1 = __shfl_xor_sync(0xffffffffu, i1, off);
        float os2 = __shfl_xor_sync(0xffffffffu, s2c, off);
        int   oi2 = __shfl_xor_sync(0xffffffffu, i2, off);
        upd(os1, oi1);
        upd(os2, oi2);
    }

    // exact fp32 refine — KEEP R8 arithmetic order exactly
    const float* f  = g_feaT + (size_t)row * DDIM;
    const float* c0 = g_cbF + (size_t)i1 * DDIM;
    const float* c1 = g_cbF + (size_t)i2 * DDIM;
    float d0 = 0.f, d1 = 0.f;
    for (int k = lane; k < DDIM; k += 32) {
        float fv = f[k];
        d0 += fv * c0[k];
        d1 += fv * c1[k];
    }
#pragma unroll
    for (int off = 16; off; off >>= 1) {
        d0 += __shfl_xor_sync(0xffffffffu, d0, off);
        d1 += __shfl_xor_sync(0xffffffffu, d1, off);
    }
    float e0 = d0 - 0.5f * g_cn2[i1];
    float e1 = d1 - 0.5f * g_cn2[i2];
    int best = (e1 > e0 || (e1 == e0 && i2 < i1)) ? i2 : i1;
    if (lane == 0) g_bi[row] = best;
}

// ---------------- gather (R9 verbatim, float4) ----------------
__global__ void gather_kernel(const float* __restrict__ cb0, const float* __restrict__ cb1,
                              const float* __restrict__ cb2, const int* __restrict__ idxp) {
    __shared__ int sbi[64];
    __shared__ float wsum[8];
    int n = blockIdx.x, tid = threadIdx.x;
    int idx = *idxp;
    const float* cbh = (idx == 1) ? cb1 : cb2;
    if (tid < 64) {
        int b = g_bi[n * 64 + tid];
        sbi[tid] = b;
        atomicAdd(&g_counts[b], 1);
    }
    __syncthreads();
    float local = 0.f;
    for (int t = tid; t < 4096; t += 256) {
        int srow = t >> 6, oc4 = (t & 63) * 4;
        int b = sbi[srow];
        const float* cp = (b < 512) ? (cb0 + (size_t)b * 256) : (cbh + (size_t)(b - 512) * 256);
        float4 q4 = *(const float4*)&cp[oc4];
        size_t r = ((size_t)n * 64 + srow) * 256 + oc4;
        float4 f4 = *(const float4*)&g_feaT[r];
        float d0 = q4.x - f4.x, d1 = q4.y - f4.y, d2 = q4.z - f4.z, d3 = q4.w - f4.w;
        local += d0 * d0 + d1 * d1 + d2 * d2 + d3 * d3;
        __nv_bfloat162 h01, l01, h23, l23;
        split2(q4.x, h01.x, l01.x); split2(q4.y, h01.y, l01.y);
        split2(q4.z, h23.x, l23.x); split2(q4.w, h23.y, l23.y);
        *(uint2*)&g_qh[r] = make_uint2(*(uint32_t*)&h01, *(uint32_t*)&h23);
        *(uint2*)&g_ql[r] = make_uint2(*(uint32_t*)&l01, *(uint32_t*)&l23);
    }
#pragma unroll
    for (int o = 16; o; o >>= 1) local += __shfl_xor_sync(0xffffffffu, local, o);
    if ((tid & 31) == 0) wsum[tid >> 5] = local;
    __syncthreads();
    if (tid == 0) {
        float t = 0.f;
        for (int w = 0; w < 8; w++) t += wsum[w];
        atomicAdd(&g_lossSum, t);
    }
}

// ---------------- prep: fc1 weight permute + split (R8 verbatim) --------------
__global__ void prep_f1w_kernel(const float* __restrict__ f1w) {
    int gid = blockIdx.x * 256 + threadIdx.x;
    int h = gid >> 14, kp = gid & 16383;
    int s = kp >> 8, oc = kp & 255;
    float v = f1w[(size_t)h * CH + oc * 64 + s];
    split2(v, g_f1wh[gid], g_f1wl[gid]);
}

// ---------------- fc1 TC GEMM (R8 verbatim) ----------------
__global__ void __launch_bounds__(256) fc1_tc_kernel(const float* __restrict__ f1b) {
    constexpr int BM = 128, BN = 64, LDK = 40, K = CH;
    constexpr int BOFF = 2 * 2 * BM * LDK;
    const __nv_bfloat16* Ag[2] = {g_qh, g_ql};
    const __nv_bfloat16* Bg[2] = {g_f1wh, g_f1wl};
    extern __shared__ __nv_bfloat16 sm[];
    const int tid = threadIdx.x;
    const int warp = tid >> 5, lane = tid & 31;
    const int wm = warp & 1, wn = warp >> 1;
    const size_t m0 = (size_t)blockIdx.y * BM;
    const int n0 = blockIdx.x * BN;

    float acc[4][2][4];
#pragma unroll
    for (int i = 0; i < 4; i++)
#pragma unroll
        for (int j = 0; j < 2; j++)
#pragma unroll
            for (int q = 0; q < 4; q++) acc[i][j][q] = 0.f;

    auto issue = [&](int kt) {
        int st = kt & 1;
        size_t kb = (size_t)kt * 32;
#pragma unroll
        for (int p = 0; p < 2; p++) {
            for (int i = tid; i < BM * 4; i += 256) {
                int r = i >> 2, c = (i & 3) * 8;
                cpasync16(s2u(&sm[((p * 2 + st) * BM + r) * LDK + c]),
                          Ag[p] + (m0 + r) * K + kb + c);
            }
            for (int i = tid; i < BN * 4; i += 256) {
                int r = i >> 2, c = (i & 3) * 8;
                cpasync16(s2u(&sm[BOFF + ((p * 2 + st) * BN + r) * LDK + c]),
                          Bg[p] + (size_t)(n0 + r) * K + kb + c);
            }
        }
        asm volatile("cp.async.commit_group;");
    };

    constexpr int NK = K / 32;
    issue(0);
    for (int kt = 0; kt < NK; kt++) {
        if (kt + 1 < NK) {
            issue(kt + 1);
            asm volatile("cp.async.wait_group 1;");
        } else {
            asm volatile("cp.async.wait_group 0;");
        }
        __syncthreads();
        int st = kt & 1;
#pragma unroll
        for (int ks = 0; ks < 2; ks++) {
            int arow = wm * 64 + (lane & 15);
            int acol = ks * 16 + (lane >> 4) * 8;
            int brow = wn * 16 + (lane & 7) + ((lane >> 4) << 3);
            int bcol = ks * 16 + ((lane >> 3) & 1) * 8;
            uint32_t a0[4][4], a1[4][4], b0[4], b1[4];
#pragma unroll
            for (int mi = 0; mi < 4; mi++) {
                ldsm4(a0[mi], s2u(&sm[((0 * 2 + st) * BM + arow + mi * 16) * LDK + acol]));
                ldsm4(a1[mi], s2u(&sm[((1 * 2 + st) * BM + arow + mi * 16) * LDK + acol]));
            }
            ldsm4(b0, s2u(&sm[BOFF + ((0 * 2 + st) * BN + brow) * LDK + bcol]));
            ldsm4(b1, s2u(&sm[BOFF + ((1 * 2 + st) * BN + brow) * LDK + bcol]));
#pragma unroll
            for (int mi = 0; mi < 4; mi++)
#pragma unroll
                for (int j = 0; j < 2; j++) {
                    mma16816(acc[mi][j], a0[mi], &b0[j * 2]);
                    mma16816(acc[mi][j], a0[mi], &b1[j * 2]);
                    mma16816(acc[mi][j], a1[mi], &b0[j * 2]);
                }
        }
        __syncthreads();
    }

#pragma unroll
    for (int mi = 0; mi < 4; mi++)
#pragma unroll
        for (int j = 0; j < 2; j++) {
            size_t row = m0 + wm * 64 + mi * 16 + (lane >> 2);
            int col = n0 + wn * 16 + j * 8 + (lane & 3) * 2;
            float* c = acc[mi][j];
#pragma unroll
            for (int half = 0; half < 2; half++) {
                size_t r = row + half * 8;
                float a0v = c[half * 2 + 0] + __ldg(&f1b[col]);
                float a1v = c[half * 2 + 1] + __ldg(&f1b[col + 1]);
                float2 o;
                o.x = 0.5f * a0v * (1.f + erff(a0v * 0.70710678118654752f));
                o.y = 0.5f * a1v * (1.f + erff(a1v * 0.70710678118654752f));
                *reinterpret_cast<float2*>(&g_h1[r * HID + col]) = o;
            }
        }
}

// ---------------- fc2 (R1 verbatim) ----------------
__global__ void fc2_kernel(const float* __restrict__ w, const float* __restrict__ b,
                           float* __restrict__ out) {
    int gwarp = (blockIdx.x * 256 + threadIdx.x) >> 5;
    int lane = threadIdx.x & 31;
    if (gwarp >= NB) return;
    float acc[10];
#pragma unroll
    for (int o = 0; o < 10; o++) acc[o] = 0.f;
    const float* hrow = g_h1 + (size_t)gwarp * HID;
    for (int k = lane; k < HID; k += 32) {
        float h = hrow[k];
#pragma unroll
        for (int o = 0; o < 10; o++) acc[o] += h * w[o * HID + k];
    }
#pragma unroll
    for (int o = 0; o < 10; o++)
#pragma unroll
        for (int off = 16; off; off >>= 1) acc[o] += __shfl_xor_sync(0xffffffffu, acc[o], off);
    if (lane == 0) {
#pragma unroll
        for (int o = 0; o < 10; o++) out[(size_t)gwarp * 10 + o] = acc[o] + b[o];
    }
}

// ---------------- finalize (R1 verbatim) ----------------
__global__ void finalize_kernel(float* __restrict__ out) {
    __shared__ float wsum[8];
    int tid = threadIdx.x;
    float local = 0.f;
    for (int k = tid; k < KMAX; k += 256) {
        float p = (float)g_counts[k] * (1.0f / 131072.0f);
        local += p * logf(p + 1e-10f);
    }
#pragma unroll
    for (int o = 16; o; o >>= 1) local += __shfl_xor_sync(0xffffffffu, local, o);
    if ((tid & 31) == 0) wsum[tid >> 5] = local;
    __syncthreads();
    if (tid == 0) {
        float t = 0.f;
        for (int w = 0; w < 8; w++) t += wsum[w];
        out[20480] = 1.25f * g_lossSum * (1.0f / 33554432.0f);
        out[20481] = expf(-t);
    }
}

// ---------------- launch ----------------
extern "C" void kernel_launch(void* const* d_in, const int* in_sizes, int n_in,
                              void* d_out, int out_size) {
    const float* x    = (const float*)d_in[0];
    const int*   idxp = (const int*)  d_in[1];
    const float* w1   = (const float*)d_in[2];
    const float* b1   = (const float*)d_in[3];
    const float* w2   = (const float*)d_in[4];
    const float* b2   = (const float*)d_in[5];
    const float* cb0  = (const float*)d_in[6];
    const float* cb1  = (const float*)d_in[7];
    const float* cb2  = (const float*)d_in[8];
    const float* f1w  = (const float*)d_in[9];
    const float* f1b  = (const float*)d_in[10];
    const float* f2w  = (const float*)d_in[11];
    const float* f2b  = (const float*)d_in[12];
    float* out = (float*)d_out;

    constexpr int SM1 = 3072 * 4 + 6144 * 8 + 128 * 4;            // 61952
    constexpr int SMC = (2 * 32 * 68 + 2 * 32 * 264) * 4;         // 84992
    constexpr int SMS = (2 * 2 * 128 + 2 * 2 * 128) * 40 * 2;     // 81920 (>= 32KB cand)
    constexpr int SMF = (2 * 2 * 128 + 2 * 2 * 64)  * 40 * 2;     // 61440
    cudaFuncSetAttribute(conv1_kernel,      cudaFuncAttributeMaxDynamicSharedMemorySize, SM1);
    cudaFuncSetAttribute(conv2_gemm_kernel, cudaFuncAttributeMaxDynamicSharedMemorySize, SMC);
    cudaFuncSetAttribute(scores_kernel,     cudaFuncAttributeMaxDynamicSharedMemorySize, SMS);
    cudaFuncSetAttribute(fc1_tc_kernel,     cudaFuncAttributeMaxDynamicSharedMemorySize, SMF);

    zero_stats_kernel<<<1, 1024>>>();
    prep_f1w_kernel<<<32768, 256>>>(f1w);
    prep_w2p_kernel<<<2048, 256>>>(w2);
    prep_codes_kernel<<<1024, 256>>>(cb0, cb1, cb2, idxp);
    conv1_kernel<<<NB, 128, SM1>>>(x, w1, b1);
    im2col_kernel<<<dim3(16, NB), 256>>>();
    conv2_gemm_kernel<<<NB, 256, SMC>>>(b2);
    scores_kernel<<<dim3(8, 1024), 256, SMS>>>();
    refine_kernel<<<NROWS / 8, 256>>>();
    gather_kernel<<<NB, 256>>>(cb0, cb1, cb2, idxp);
    fc1_tc_kernel<<<dim3(8, 16), 256, SMF>>>(f1b);
    fc2_kernel<<<NB / 8, 256>>>(f2w, f2b, out);
    finalize_kernel<<<1, 256>>>(out);
}